// round 8
// baseline (speedup 1.0000x reference)
#include <cuda_runtime.h>

// out[b, d] = initial[b, d] * (sum_k X[b,k]*alphas[k]) + X[b,d] + bias[d]
// B = 16384 rows, D = 2048 cols, fp32.
//
// Warp-per-row, two-pass, ZERO barriers / ZERO shared memory.
// Pass 1: warp streams its X row (default cache policy -> stays in L1/L2),
//         accumulates the dot product, reduces with 5 warp shuffles.
// Pass 2: re-reads X (cache hit, no extra DRAM), streams initial, writes out.
// Every warp proceeds fully independently -- no phase-aligned bursts.

#define THREADS 256
#define D_DIM 2048
#define D4 (D_DIM / 4)              // 512 float4 per row
#define V_PER_LANE (D4 / 32)        // 16 float4 per lane per row
#define WARPS_PER_CTA (THREADS / 32)

__global__ __launch_bounds__(THREADS, 8)
void crossnet_kernel(const float* __restrict__ initial,
                     const float* __restrict__ X,
                     const float* __restrict__ alphas,
                     const float* __restrict__ bias,
                     float* __restrict__ out)
{
    const int lane = threadIdx.x & 31;
    const int wid  = threadIdx.x >> 5;
    const int row  = blockIdx.x * WARPS_PER_CTA + wid;

    const float4* __restrict__ X4 = reinterpret_cast<const float4*>(X) + (size_t)row * D4;
    const float4* __restrict__ I4 = reinterpret_cast<const float4*>(initial) + (size_t)row * D4;
    const float4* __restrict__ A4 = reinterpret_cast<const float4*>(alphas);
    const float4* __restrict__ B4 = reinterpret_cast<const float4*>(bias);
    float4* __restrict__ O4 = reinterpret_cast<float4*>(out) + (size_t)row * D4;

    // ---- Pass 1: dot product over the row (X cached for pass 2) ----
    float dot = 0.0f;
    #pragma unroll
    for (int v = 0; v < V_PER_LANE; v++) {
        const int idx = v * 32 + lane;
        float4 x = X4[idx];          // default policy: keep in L1/L2
        float4 a = A4[idx];          // hot across all rows
        dot += x.x * a.x + x.y * a.y + x.z * a.z + x.w * a.w;
    }

    // Warp reduce (no smem, no barrier).
    #pragma unroll
    for (int off = 16; off > 0; off >>= 1)
        dot += __shfl_xor_sync(0xFFFFFFFFu, dot, off);
    const float scale = dot;         // all lanes hold the full sum

    // ---- Pass 2: epilogue. X re-read hits L1/L2; initial streams. ----
    #pragma unroll
    for (int v = 0; v < V_PER_LANE; v++) {
        const int idx = v * 32 + lane;
        float4 x = X4[idx];          // cache hit
        float4 i = __ldcs(&I4[idx]); // single-use -> evict-first
        float4 b = B4[idx];
        float4 o;
        o.x = fmaf(i.x, scale, x.x + b.x);
        o.y = fmaf(i.y, scale, x.y + b.y);
        o.z = fmaf(i.z, scale, x.z + b.z);
        o.w = fmaf(i.w, scale, x.w + b.w);
        __stcs(&O4[idx], o);         // write-once -> streaming store
    }
}

extern "C" void kernel_launch(void* const* d_in, const int* in_sizes, int n_in,
                              void* d_out, int out_size)
{
    const float* initial = (const float*)d_in[0];
    const float* X       = (const float*)d_in[1];
    const float* alphas  = (const float*)d_in[2];
    const float* bias    = (const float*)d_in[3];
    float* out           = (float*)d_out;

    const int B = in_sizes[0] / D_DIM;   // 16384
    crossnet_kernel<<<B / WARPS_PER_CTA, THREADS>>>(initial, X, alphas, bias, out);
}

// round 9
// speedup vs baseline: 2.0444x; 2.0444x over previous
#include <cuda_runtime.h>

// out[b, d] = initial[b, d] * (sum_k X[b,k]*alphas[k]) + X[b,d] + bias[d]
// B = 16384 rows, D = 2048 cols, fp32.
//
// Best configuration found (R7): TWO rows per CTA, 512 threads.
// Each thread covers exactly 1 float4 per row per array (32 regs ->
// 3 CTAs/SM, ~89% occupancy) while one barrier + one smem round-trip
// serves both row reductions. Single-pass: X lives in registers for both
// the dot product and the epilogue (minimum 384 MB DRAM traffic).
// Measured: 54.1 us kernel, 83.7% DRAM-active, 6.63 TB/s.

#define THREADS 512
#define D_DIM 2048
#define D4 (D_DIM / 4)          // 512 float4 per row == THREADS
#define NWARPS (THREADS / 32)   // 16

__global__ __launch_bounds__(THREADS, 3)
void crossnet_kernel(const float* __restrict__ initial,
                     const float* __restrict__ X,
                     const float* __restrict__ alphas,
                     const float* __restrict__ bias,
                     float* __restrict__ out)
{
    const int t = threadIdx.x;
    const int lane = t & 31;
    const int wid = t >> 5;

    const size_t base0 = (size_t)(2 * blockIdx.x) * D4;
    const size_t base1 = base0 + D4;

    const float4* __restrict__ X4 = reinterpret_cast<const float4*>(X);
    const float4* __restrict__ I4 = reinterpret_cast<const float4*>(initial);
    const float4* __restrict__ A4 = reinterpret_cast<const float4*>(alphas);
    const float4* __restrict__ B4 = reinterpret_cast<const float4*>(bias);
    float4* __restrict__ O4 = reinterpret_cast<float4*>(out);

    // Front-batched loads: 4 streaming LDG.128 + 2 cached (alphas/bias hot).
    float4 x0 = __ldcs(&X4[base0 + t]);
    float4 x1 = __ldcs(&X4[base1 + t]);
    float4 i0 = __ldcs(&I4[base0 + t]);
    float4 i1 = __ldcs(&I4[base1 + t]);
    float4 a  = A4[t];
    float4 b  = B4[t];

    // Per-thread partial dot products for both rows.
    float dot0 = x0.x * a.x + x0.y * a.y + x0.z * a.z + x0.w * a.w;
    float dot1 = x1.x * a.x + x1.y * a.y + x1.z * a.z + x1.w * a.w;

    // Warp reduce both rows.
    #pragma unroll
    for (int off = 16; off > 0; off >>= 1) {
        dot0 += __shfl_xor_sync(0xFFFFFFFFu, dot0, off);
        dot1 += __shfl_xor_sync(0xFFFFFFFFu, dot1, off);
    }

    // Single-barrier block reduce over 16 warps; every warp folds the
    // partials redundantly via shuffle (no second barrier).
    __shared__ float ws0[NWARPS];
    __shared__ float ws1[NWARPS];
    if (lane == 0) { ws0[wid] = dot0; ws1[wid] = dot1; }
    __syncthreads();

    float s0 = (lane < NWARPS) ? ws0[lane] : 0.0f;
    float s1 = (lane < NWARPS) ? ws1[lane] : 0.0f;
    #pragma unroll
    for (int off = NWARPS / 2; off > 0; off >>= 1) {
        s0 += __shfl_xor_sync(0xFFFFFFFFu, s0, off);
        s1 += __shfl_xor_sync(0xFFFFFFFFu, s1, off);
    }
    const float scale0 = __shfl_sync(0xFFFFFFFFu, s0, 0);
    const float scale1 = __shfl_sync(0xFFFFFFFFu, s1, 0);

    float4 o;
    o.x = fmaf(i0.x, scale0, x0.x + b.x);
    o.y = fmaf(i0.y, scale0, x0.y + b.y);
    o.z = fmaf(i0.z, scale0, x0.z + b.z);
    o.w = fmaf(i0.w, scale0, x0.w + b.w);
    __stcs(&O4[base0 + t], o);

    o.x = fmaf(i1.x, scale1, x1.x + b.x);
    o.y = fmaf(i1.y, scale1, x1.y + b.y);
    o.z = fmaf(i1.z, scale1, x1.z + b.z);
    o.w = fmaf(i1.w, scale1, x1.w + b.w);
    __stcs(&O4[base1 + t], o);
}

extern "C" void kernel_launch(void* const* d_in, const int* in_sizes, int n_in,
                              void* d_out, int out_size)
{
    const float* initial = (const float*)d_in[0];
    const float* X       = (const float*)d_in[1];
    const float* alphas  = (const float*)d_in[2];
    const float* bias    = (const float*)d_in[3];
    float* out           = (float*)d_out;

    const int B = in_sizes[0] / D_DIM;   // 16384
    crossnet_kernel<<<B / 2, THREADS>>>(initial, X, alphas, bias, out);
}